// round 4
// baseline (speedup 1.0000x reference)
#include <cuda_runtime.h>
#include <math.h>

// Problem constants (fixed by the reference)
#define BB  4
#define TT  1024
#define EE  512
#define HH  8
#define EHD (EE*HH)   // 4096
#define BT  (BB*TT)   // 4096

// Scratch (device globals: allocation-free rule)
__device__ float g_Q[(size_t)BT*EHD];            // 64 MB
__device__ float g_K[(size_t)BT*EHD];            // 64 MB
__device__ float g_V[(size_t)BT*EHD];            // 64 MB
__device__ float g_S[(size_t)BB*HH*TT*TT];       // 128 MB scores/probs
__device__ float g_A[(size_t)BT*EHD];            // 64 MB attn out (b,t,h*e)

// ---------------------------------------------------------------------------
// Generic 128x128 tile SGEMM, BK=8, 256 threads, 8x8 per thread.
// C[m,n] = scale * sum_k A[m,k] * B'[k,n]  (+ bias[n])
//   BNT=1: B stored [N,K] row-major (B' = B^T)   -> "NT"
//   BNT=0: B stored [K,N] row-major              -> "NN"
// Batched over blockIdx.z with (z>>3, z&7) two-level stride decomposition
// (works for (b,h) batching with H=8, and for plain linear batching).
// causal=1: skip tiles fully above the diagonal (bn > bm).
// All M,N assumed multiples of 128, K multiple of 8 (true for every call).
// ---------------------------------------------------------------------------
template<int BNT>
__global__ __launch_bounds__(256) void gemm128(
    int K,
    const float* __restrict__ A, int lda, size_t sAo, size_t sAi,
    const float* __restrict__ Bm, int ldb, size_t sBo, size_t sBi,
    float* __restrict__ C, int ldc, size_t sCo, size_t sCi,
    float scale, const float* __restrict__ bias, int causal)
{
    const int bm = blockIdx.y * 128;
    const int bn = blockIdx.x * 128;
    if (causal && bn > bm) return;  // tiles are 128-aligned: bn>bm <=> fully masked

    const int bz = blockIdx.z;
    A  += (size_t)(bz >> 3) * sAo + (size_t)(bz & 7) * sAi;
    Bm += (size_t)(bz >> 3) * sBo + (size_t)(bz & 7) * sBi;
    C  += (size_t)(bz >> 3) * sCo + (size_t)(bz & 7) * sCi;

    __shared__ float As[8][128];
    __shared__ float Bs[8][128];

    const int tid = threadIdx.x;
    const int tx  = tid & 15;      // 0..15 -> N direction
    const int ty  = tid >> 4;      // 0..15 -> M direction

    const int arow = tid >> 1;          // 0..127
    const int acol = (tid & 1) << 2;    // 0 or 4

    float acc[8][8];
#pragma unroll
    for (int i = 0; i < 8; i++)
#pragma unroll
        for (int j = 0; j < 8; j++) acc[i][j] = 0.f;

    for (int k0 = 0; k0 < K; k0 += 8) {
        // Load A tile (rows bm..bm+127, cols k0..k0+7), transpose into As[k][m]
        float4 av = *(const float4*)(A + (size_t)(bm + arow) * lda + k0 + acol);
        As[acol+0][arow] = av.x;
        As[acol+1][arow] = av.y;
        As[acol+2][arow] = av.z;
        As[acol+3][arow] = av.w;

        if (BNT) {
            // B [N,K]: same pattern as A
            float4 bv = *(const float4*)(Bm + (size_t)(bn + arow) * ldb + k0 + acol);
            Bs[acol+0][arow] = bv.x;
            Bs[acol+1][arow] = bv.y;
            Bs[acol+2][arow] = bv.z;
            Bs[acol+3][arow] = bv.w;
        } else {
            // B [K,N]: rows k0..k0+7, cols bn..bn+127 (contiguous in n)
            const int krow = tid >> 5;            // 0..7
            const int kcol = (tid & 31) << 2;     // 0..124
            float4 bv = *(const float4*)(Bm + (size_t)(k0 + krow) * ldb + bn + kcol);
            *(float4*)&Bs[krow][kcol] = bv;
        }
        __syncthreads();

#pragma unroll
        for (int kk = 0; kk < 8; kk++) {
            float4 a0 = *(const float4*)&As[kk][ty << 2];
            float4 a1 = *(const float4*)&As[kk][64 + (ty << 2)];
            float4 b0 = *(const float4*)&Bs[kk][tx << 2];
            float4 b1 = *(const float4*)&Bs[kk][64 + (tx << 2)];
            float a[8] = {a0.x, a0.y, a0.z, a0.w, a1.x, a1.y, a1.z, a1.w};
            float b[8] = {b0.x, b0.y, b0.z, b0.w, b1.x, b1.y, b1.z, b1.w};
#pragma unroll
            for (int i = 0; i < 8; i++)
#pragma unroll
                for (int j = 0; j < 8; j++)
                    acc[i][j] += a[i] * b[j];
        }
        __syncthreads();
    }

    // Epilogue: scale, optional bias, vectorized stores
#pragma unroll
    for (int i = 0; i < 8; i++) {
        const int r = bm + ((i < 4) ? ((ty << 2) + i) : (64 + (ty << 2) + i - 4));
#pragma unroll
        for (int jg = 0; jg < 2; jg++) {
            const int c0 = bn + jg * 64 + (tx << 2);
            float4 v;
            v.x = acc[i][jg*4+0] * scale;
            v.y = acc[i][jg*4+1] * scale;
            v.z = acc[i][jg*4+2] * scale;
            v.w = acc[i][jg*4+3] * scale;
            if (bias) {
                v.x += bias[c0+0]; v.y += bias[c0+1];
                v.z += bias[c0+2]; v.w += bias[c0+3];
            }
            *(float4*)&C[(size_t)r * ldc + c0] = v;
        }
    }
}

// ---------------------------------------------------------------------------
// Causal softmax over rows of g_S. One block (256 thr) per row.
// Row layout: row = (b*H + h)*T + q; valid entries [0, q], zeros written above.
// ---------------------------------------------------------------------------
__global__ __launch_bounds__(256) void softmax_causal(float* __restrict__ S)
{
    const int row = blockIdx.x;
    const int q   = row & (TT - 1);
    const int len = q + 1;
    float* Sr = S + (size_t)row * TT;

    __shared__ float sh[8];
    const int tid = threadIdx.x;

    float m = -1e30f;
    for (int i = tid; i < len; i += 256) m = fmaxf(m, Sr[i]);
#pragma unroll
    for (int o = 16; o > 0; o >>= 1) m = fmaxf(m, __shfl_xor_sync(0xffffffffu, m, o));
    if ((tid & 31) == 0) sh[tid >> 5] = m;
    __syncthreads();
    m = fmaxf(fmaxf(fmaxf(sh[0], sh[1]), fmaxf(sh[2], sh[3])),
              fmaxf(fmaxf(sh[4], sh[5]), fmaxf(sh[6], sh[7])));
    __syncthreads();

    float s = 0.f;
    for (int i = tid; i < len; i += 256) {
        float e = __expf(Sr[i] - m);
        Sr[i] = e;
        s += e;
    }
#pragma unroll
    for (int o = 16; o > 0; o >>= 1) s += __shfl_xor_sync(0xffffffffu, s, o);
    if ((tid & 31) == 0) sh[tid >> 5] = s;
    __syncthreads();
    s = sh[0]+sh[1]+sh[2]+sh[3]+sh[4]+sh[5]+sh[6]+sh[7];
    const float inv = 1.0f / s;

    for (int i = tid; i < len; i += 256) Sr[i] *= inv;
    for (int i = len + tid; i < TT; i += 256) Sr[i] = 0.f;
}

// ---------------------------------------------------------------------------
extern "C" void kernel_launch(void* const* d_in, const int* in_sizes, int n_in,
                              void* d_out, int out_size)
{
    const float* x   = (const float*)d_in[0];
    const float* w_k = (const float*)d_in[1];
    const float* w_q = (const float*)d_in[2];
    const float* w_v = (const float*)d_in[3];
    const float* w_u = (const float*)d_in[4];
    const float* b_u = (const float*)d_in[5];
    float* out = (float*)d_out;

    void *pQ, *pK, *pV, *pS, *pA;
    cudaGetSymbolAddress(&pQ, g_Q);
    cudaGetSymbolAddress(&pK, g_K);
    cudaGetSymbolAddress(&pV, g_V);
    cudaGetSymbolAddress(&pS, g_S);
    cudaGetSymbolAddress(&pA, g_A);
    float* Q  = (float*)pQ;
    float* Kb = (float*)pK;
    float* V  = (float*)pV;
    float* Sc = (float*)pS;
    float* Ab = (float*)pA;

    const float s = 0.21022410381342864f;  // 512^(-1/4), folded into Q and K

    const dim3 blk(256);
    const size_t zero = 0;

    // 1) Projections: [4096,4096] = x[4096,512] @ W^T, W is [4096,512]
    gemm128<1><<<dim3(32, 32, 1), blk>>>(EE,
        x, EE, zero, zero,  w_q, EE, zero, zero,  Q,  EHD, zero, zero, s,   nullptr, 0);
    gemm128<1><<<dim3(32, 32, 1), blk>>>(EE,
        x, EE, zero, zero,  w_k, EE, zero, zero,  Kb, EHD, zero, zero, s,   nullptr, 0);
    gemm128<1><<<dim3(32, 32, 1), blk>>>(EE,
        x, EE, zero, zero,  w_v, EE, zero, zero,  V,  EHD, zero, zero, 1.f, nullptr, 0);

    // 2) Scores: per (b,h): S[q,k] = Q_bh[q,:] . K_bh[k,:], causal tile skip
    gemm128<1><<<dim3(8, 8, 32), blk>>>(EE,
        Q,  EHD, (size_t)TT*EHD, (size_t)EE,
        Kb, EHD, (size_t)TT*EHD, (size_t)EE,
        Sc, TT,  (size_t)HH*TT*TT, (size_t)TT*TT,
        1.f, nullptr, 1);

    // 3) Causal softmax (writes zeros above the diagonal)
    softmax_causal<<<BB*HH*TT, 256>>>(Sc);

    // 4) PV: per (b,h): O[q,d] = sum_t P[q,t] * V_bh[t,d]   (NN form)
    gemm128<0><<<dim3(4, 8, 32), blk>>>(TT,
        Sc, TT,  (size_t)HH*TT*TT, (size_t)TT*TT,
        V,  EHD, (size_t)TT*EHD,   (size_t)EE,
        Ab, EHD, (size_t)TT*EHD,   (size_t)EE,
        1.f, nullptr, 0);

    // 5) Unify: out[4096,512] = Ab[4096,4096] @ w_u^T + b_u
    gemm128<1><<<dim3(4, 32, 1), blk>>>(EHD,
        Ab,  EHD, zero, zero,  w_u, EHD, zero, zero,  out, EE, zero, zero,
        1.f, b_u, 0);
}

// round 6
// speedup vs baseline: 3.6238x; 3.6238x over previous
#include <cuda_runtime.h>
#include <math.h>
#include <stdint.h>

#define BB  4
#define TT  1024
#define EE  512
#define HH  8
#define EHD (EE*HH)   // 4096
#define BT  (BB*TT)   // 4096

// Scratch (device globals: allocation-free rule)
__device__ float g_Q[(size_t)BT*EHD];
__device__ float g_K[(size_t)BT*EHD];
__device__ float g_V[(size_t)BT*EHD];
__device__ float g_S[(size_t)BB*HH*TT*TT];
__device__ float g_A[(size_t)BT*EHD];

// ---------------- helpers ---------------------------------------------------
__device__ __forceinline__ uint32_t smem_u32(const void* p) {
    uint32_t a;
    asm("{ .reg .u64 t; cvta.to.shared.u64 t, %1; cvt.u32.u64 %0, t; }"
        : "=r"(a) : "l"(p));
    return a;
}
__device__ __forceinline__ void cp16(uint32_t dst, const void* src) {
    asm volatile("cp.async.cg.shared.global [%0], [%1], 16;"
                 :: "r"(dst), "l"(src) : "memory");
}
__device__ __forceinline__ uint32_t tf32(float f) {
    uint32_t r;
    asm("cvt.rna.tf32.f32 %0, %1;" : "=r"(r) : "f"(f));
    return r;
}
__device__ __forceinline__ void mma_tf32(float* c, const uint32_t* a,
                                         const uint32_t* b) {
    asm volatile(
        "mma.sync.aligned.m16n8k8.row.col.f32.tf32.tf32.f32 "
        "{%0,%1,%2,%3}, {%4,%5,%6,%7}, {%8,%9}, {%0,%1,%2,%3};"
        : "+f"(c[0]), "+f"(c[1]), "+f"(c[2]), "+f"(c[3])
        : "r"(a[0]), "r"(a[1]), "r"(a[2]), "r"(a[3]),
          "r"(b[0]), "r"(b[1]));
}

// SMEM geometry (fp32 words)
#define A_LD   36        // 128 rows x 32 cols, pad 36  (bank = 4m+k mod 32: perm)
#define BN_LD  36        // NT B: [n][k] same as A
#define BK_LDW 136       // NN B: [k=32][n=128], pad 136 (bank = 8k+n mod 32: perm)
#define A_WORDS   (128*A_LD)          // 4608
#define B_WORDS   4608                // max(128*36, 32*136=4352)
#define STAGE_W   (A_WORDS + B_WORDS) // 9216 words = 36KB
#define SMSZ      (2*STAGE_W*4)       // 73728 B

// ---------------------------------------------------------------------------
// TF32 HMMA GEMM, 128x128 tile, BK=32, 8 warps (4x2), 32x64 per warp.
// C = scale * A[M,K] @ B'[K,N] + bias.  BNT=1: B is [N,K] (NT). BNT=0: [K,N].
// Batched over blockIdx.z = (zo*8 + zi). causal: skip bn>bm. kclip: K=bm+128.
// ---------------------------------------------------------------------------
template<int BNT>
__global__ __launch_bounds__(256) void gemm_tf32(
    int K,
    const float* __restrict__ A, int lda, size_t sAo, size_t sAi,
    const float* __restrict__ Bm, int ldb, size_t sBo, size_t sBi,
    float* __restrict__ C, int ldc, size_t sCo, size_t sCi,
    float scale, const float* __restrict__ bias, int causal, int kclip)
{
    const int bm = blockIdx.y * 128, bn = blockIdx.x * 128;
    if (causal && bn > bm) return;

    const size_t zo = blockIdx.z >> 3, zi = blockIdx.z & 7;
    A  += zo * sAo + zi * sAi;
    Bm += zo * sBo + zi * sBi;
    C  += zo * sCo + zi * sCi;

    extern __shared__ float sm[];
    const uint32_t sbase = smem_u32(sm);

    const int tid  = threadIdx.x;
    const int wid  = tid >> 5, lane = tid & 31;
    const int wm   = wid >> 1, wn = wid & 1;       // 4 x 2 warp grid
    const int arow = wm * 32;                      // warp M offset
    const int bcol = wn * 64;                      // warp N offset
    const int lg   = lane >> 2, lt = lane & 3;     // group / in-group

    const int Keff = kclip ? min(K, bm + 128) : K;
    const int nch  = Keff >> 5;

    float acc[2][8][4];
#pragma unroll
    for (int mt = 0; mt < 2; mt++)
#pragma unroll
        for (int nt = 0; nt < 8; nt++)
#pragma unroll
            for (int i = 0; i < 4; i++) acc[mt][nt][i] = 0.f;

    // ---- async tile loader for stage `c` into buffer c&1 ----
    auto prefetch = [&](int c) {
        const int k0  = c << 5;
        const uint32_t sA = sbase + (uint32_t)((c & 1) * STAGE_W) * 4;
        const uint32_t sB = sA + A_WORDS * 4;
#pragma unroll
        for (int i = 0; i < 4; i++) {
            const int e = tid + i * 256;
            const int r = e >> 3, cw = (e & 7) * 4;
            cp16(sA + (r * A_LD + cw) * 4,
                 A + (size_t)(bm + r) * lda + k0 + cw);
        }
        if (BNT) {
#pragma unroll
            for (int i = 0; i < 4; i++) {
                const int e = tid + i * 256;
                const int r = e >> 3, cw = (e & 7) * 4;
                cp16(sB + (r * BN_LD + cw) * 4,
                     Bm + (size_t)(bn + r) * ldb + k0 + cw);
            }
        } else {
#pragma unroll
            for (int i = 0; i < 4; i++) {
                const int e = tid + i * 256;
                const int r = e >> 5, cw = (e & 31) * 4;
                cp16(sB + (r * BK_LDW + cw) * 4,
                     Bm + (size_t)(k0 + r) * ldb + bn + cw);
            }
        }
        asm volatile("cp.async.commit_group;" ::: "memory");
    };

    prefetch(0);

    for (int c = 0; c < nch; c++) {
        const bool hasnext = (c + 1 < nch);
        if (hasnext) prefetch(c + 1);
        if (hasnext) asm volatile("cp.async.wait_group 1;" ::: "memory");
        else         asm volatile("cp.async.wait_group 0;" ::: "memory");
        __syncthreads();

        const float* As = sm + (c & 1) * STAGE_W;
        const float* Bs = As + A_WORDS;

#pragma unroll
        for (int ks = 0; ks < 4; ks++) {
            const int kf = ks * 8 + lt;
            uint32_t a[2][4], b[8][2];
#pragma unroll
            for (int mt = 0; mt < 2; mt++) {
                const int m = arow + mt * 16 + lg;
                a[mt][0] = tf32(As[m * A_LD + kf]);
                a[mt][1] = tf32(As[(m + 8) * A_LD + kf]);
                a[mt][2] = tf32(As[m * A_LD + kf + 4]);
                a[mt][3] = tf32(As[(m + 8) * A_LD + kf + 4]);
            }
#pragma unroll
            for (int nt = 0; nt < 8; nt++) {
                if (BNT) {
                    const int n = bcol + nt * 8 + lg;
                    b[nt][0] = tf32(Bs[n * BN_LD + kf]);
                    b[nt][1] = tf32(Bs[n * BN_LD + kf + 4]);
                } else {
                    const int n = bcol + nt * 8 + lg;
                    b[nt][0] = tf32(Bs[(ks * 8 + lt) * BK_LDW + n]);
                    b[nt][1] = tf32(Bs[(ks * 8 + lt + 4) * BK_LDW + n]);
                }
            }
#pragma unroll
            for (int mt = 0; mt < 2; mt++)
#pragma unroll
                for (int nt = 0; nt < 8; nt++)
                    mma_tf32(acc[mt][nt], a[mt], b[nt]);
        }
        __syncthreads();
    }

    // ---- epilogue: direct fp32 stores (float2 per c-pair) ----
#pragma unroll
    for (int mt = 0; mt < 2; mt++) {
#pragma unroll
        for (int nt = 0; nt < 8; nt++) {
            const int gn = bn + bcol + nt * 8 + 2 * lt;
            const float bx = bias ? bias[gn] : 0.f;
            const float by = bias ? bias[gn + 1] : 0.f;
            const int r0 = bm + arow + mt * 16 + lg;
            float2 v0, v1;
            v0.x = acc[mt][nt][0] * scale + bx;
            v0.y = acc[mt][nt][1] * scale + by;
            v1.x = acc[mt][nt][2] * scale + bx;
            v1.y = acc[mt][nt][3] * scale + by;
            *(float2*)&C[(size_t)r0 * ldc + gn]       = v0;
            *(float2*)&C[(size_t)(r0 + 8) * ldc + gn] = v1;
        }
    }
}

// ---------------------------------------------------------------------------
// Causal softmax over rows of g_S (same as the passing round-3 version).
// ---------------------------------------------------------------------------
__global__ __launch_bounds__(256) void softmax_causal(float* __restrict__ S)
{
    const int row = blockIdx.x;
    const int q   = row & (TT - 1);
    const int len = q + 1;
    float* Sr = S + (size_t)row * TT;

    __shared__ float sh[8];
    const int tid = threadIdx.x;

    float m = -1e30f;
    for (int i = tid; i < len; i += 256) m = fmaxf(m, Sr[i]);
#pragma unroll
    for (int o = 16; o > 0; o >>= 1) m = fmaxf(m, __shfl_xor_sync(0xffffffffu, m, o));
    if ((tid & 31) == 0) sh[tid >> 5] = m;
    __syncthreads();
    m = fmaxf(fmaxf(fmaxf(sh[0], sh[1]), fmaxf(sh[2], sh[3])),
              fmaxf(fmaxf(sh[4], sh[5]), fmaxf(sh[6], sh[7])));
    __syncthreads();

    float s = 0.f;
    for (int i = tid; i < len; i += 256) {
        float e = __expf(Sr[i] - m);
        Sr[i] = e;
        s += e;
    }
#pragma unroll
    for (int o = 16; o > 0; o >>= 1) s += __shfl_xor_sync(0xffffffffu, s, o);
    if ((tid & 31) == 0) sh[tid >> 5] = s;
    __syncthreads();
    s = sh[0]+sh[1]+sh[2]+sh[3]+sh[4]+sh[5]+sh[6]+sh[7];
    const float inv = 1.0f / s;

    for (int i = tid; i < len; i += 256) Sr[i] *= inv;
    for (int i = len + tid; i < TT; i += 256) Sr[i] = 0.f;
}

// ---------------------------------------------------------------------------
extern "C" void kernel_launch(void* const* d_in, const int* in_sizes, int n_in,
                              void* d_out, int out_size)
{
    const float* x   = (const float*)d_in[0];
    const float* w_k = (const float*)d_in[1];
    const float* w_q = (const float*)d_in[2];
    const float* w_v = (const float*)d_in[3];
    const float* w_u = (const float*)d_in[4];
    const float* b_u = (const float*)d_in[5];
    float* out = (float*)d_out;

    void *pQ, *pK, *pV, *pS, *pA;
    cudaGetSymbolAddress(&pQ, g_Q);
    cudaGetSymbolAddress(&pK, g_K);
    cudaGetSymbolAddress(&pV, g_V);
    cudaGetSymbolAddress(&pS, g_S);
    cudaGetSymbolAddress(&pA, g_A);
    float* Q  = (float*)pQ;
    float* Kb = (float*)pK;
    float* V  = (float*)pV;
    float* Sc = (float*)pS;
    float* Ab = (float*)pA;

    static int init = 0;
    if (!init) {
        cudaFuncSetAttribute(gemm_tf32<1>,
            cudaFuncAttributeMaxDynamicSharedMemorySize, SMSZ);
        cudaFuncSetAttribute(gemm_tf32<0>,
            cudaFuncAttributeMaxDynamicSharedMemorySize, SMSZ);
        init = 1;
    }

    const float s = 0.21022410381342864f;  // 512^(-1/4), folded into Q and K
    const dim3 blk(256);
    const size_t z = 0;

    // 1) Projections: [4096,4096] = x[4096,512] @ W^T (NT)
    gemm_tf32<1><<<dim3(32, 32, 1), blk, SMSZ>>>(EE,
        x, EE, z, z,  w_q, EE, z, z,  Q,  EHD, z, z, s,   nullptr, 0, 0);
    gemm_tf32<1><<<dim3(32, 32, 1), blk, SMSZ>>>(EE,
        x, EE, z, z,  w_k, EE, z, z,  Kb, EHD, z, z, s,   nullptr, 0, 0);
    gemm_tf32<1><<<dim3(32, 32, 1), blk, SMSZ>>>(EE,
        x, EE, z, z,  w_v, EE, z, z,  V,  EHD, z, z, 1.f, nullptr, 0, 0);

    // 2) Scores: per (b,h): S = Q_bh @ K_bh^T, causal tile skip (NT)
    gemm_tf32<1><<<dim3(8, 8, 32), blk, SMSZ>>>(EE,
        Q,  EHD, (size_t)TT*EHD, (size_t)EE,
        Kb, EHD, (size_t)TT*EHD, (size_t)EE,
        Sc, TT,  (size_t)HH*TT*TT, (size_t)TT*TT,
        1.f, nullptr, 1, 0);

    // 3) Causal softmax (zeros above the diagonal)
    softmax_causal<<<BB*HH*TT, 256>>>(Sc);

    // 4) PV: per (b,h): O = P @ V  (NN, K clipped by causality)
    gemm_tf32<0><<<dim3(4, 8, 32), blk, SMSZ>>>(TT,
        Sc, TT,  (size_t)HH*TT*TT, (size_t)TT*TT,
        V,  EHD, (size_t)TT*EHD,   (size_t)EE,
        Ab, EHD, (size_t)TT*EHD,   (size_t)EE,
        1.f, nullptr, 0, 1);

    // 5) Unify: out = Ab @ w_u^T + b_u (NT)
    gemm_tf32<1><<<dim3(4, 32, 1), blk, SMSZ>>>(EHD,
        Ab,  EHD, z, z,  w_u, EHD, z, z,  out, EE, z, z,
        1.f, b_u, 0, 0);
}